// round 1
// baseline (speedup 1.0000x reference)
#include <cuda_runtime.h>

// Problem constants
#define BATCH 128
#define NIN   1152
#define DIN   8
#define NOUT  10
#define DDIM  16
#define FDIM  160          // NOUT*DDIM
#define SQ_EPS 1e-7f

// u_hat scratch: [BATCH][NIN][NOUT*DDIM] fp32 = 94.4 MB
__device__ float g_uhat[(size_t)BATCH * NIN * FDIM];

// ---------------------------------------------------------------------------
// K1: u_hat[b,i,j,d] = sum_k W[i,j,d,k] * x[b,i,k]
// One block per input capsule i. W[i] and x[:,i,:] staged in SMEM; each thread
// owns one (f = j*16+d, b-parity) slot and streams over b. Writes coalesced.
// ---------------------------------------------------------------------------
__global__ __launch_bounds__(320) void k1_uhat(const float* __restrict__ x,
                                               const float* __restrict__ W) {
    const int i = blockIdx.x;                 // 0..1151
    __shared__ __align__(16) float Ws[FDIM * DIN];   // 5 KB
    __shared__ __align__(16) float xs[BATCH * DIN];  // 4 KB
    const int tid = threadIdx.x;

    for (int t = tid; t < FDIM * DIN; t += 320)
        Ws[t] = W[(size_t)i * (FDIM * DIN) + t];
    for (int t = tid; t < BATCH * DIN; t += 320) {
        const int b = t / DIN, k = t % DIN;
        xs[t] = x[((size_t)b * NIN + i) * DIN + k];
    }
    __syncthreads();

    const int f  = tid % FDIM;   // j*16+d
    const int b0 = tid / FDIM;   // 0 or 1

    float w[DIN];
#pragma unroll
    for (int k = 0; k < DIN; k++) w[k] = Ws[f * DIN + k];

    for (int b = b0; b < BATCH; b += 2) {
        const float4 xa = *reinterpret_cast<const float4*>(&xs[b * DIN]);
        const float4 xb = *reinterpret_cast<const float4*>(&xs[b * DIN + 4]);
        float acc;
        acc = w[0] * xa.x;
        acc = fmaf(w[1], xa.y, acc);
        acc = fmaf(w[2], xa.z, acc);
        acc = fmaf(w[3], xa.w, acc);
        acc = fmaf(w[4], xb.x, acc);
        acc = fmaf(w[5], xb.y, acc);
        acc = fmaf(w[6], xb.z, acc);
        acc = fmaf(w[7], xb.w, acc);
        g_uhat[((size_t)b * NIN + i) * FDIM + f] = acc;
    }
}

// ---------------------------------------------------------------------------
// K2: fused 3-iteration dynamic routing. One block (512 thr = 16 warps) per b.
// Logits never materialized: b_t(i,j) = u_hat[i,j,:] . (v0+...+v_{t-1}).
// Warp layout: 3 groups x 10 lanes; lane owns capsule j (16 floats), a group
// handles one input capsule i per step -> 3 i's per warp step, coalesced
// 4x LDG.128 per lane.
// ---------------------------------------------------------------------------
__global__ __launch_bounds__(512) void k2_route(const float* __restrict__ bias,
                                                float* __restrict__ out) {
    const int b   = blockIdx.x;
    const int tid = threadIdx.x;
    const int w   = tid >> 5;        // warp 0..15
    const int l   = tid & 31;        // lane
    const bool active = (l < 30);
    const int g = active ? (l / 10) : 0;   // group 0..2
    const int j = active ? (l % 10) : 0;   // output capsule

    __shared__ float s_part[16][FDIM];   // per-warp partial s (10 KB)
    __shared__ float s_red[FDIM];
    __shared__ float vsum_sm[FDIM];      // v0 + v1 (+...)
    __shared__ float vlast_sm[FDIM];     // most recent v
    __shared__ float bias_sm[FDIM];

    if (tid < FDIM) bias_sm[tid] = bias[tid];

    const float* __restrict__ ubase = g_uhat + (size_t)b * NIN * FDIM;
    const unsigned FULL = 0xFFFFFFFFu;

    for (int pass = 0; pass < 3; ++pass) {
        float vr[DDIM];
        if (pass > 0) {
#pragma unroll
            for (int d = 0; d < DDIM; d++) vr[d] = vsum_sm[j * DDIM + d];
        }
        float sacc[DDIM];
#pragma unroll
        for (int d = 0; d < DDIM; d++) sacc[d] = 0.f;

        // each warp covers 72 consecutive i's, 3 per step
        for (int it = 0; it < 24; ++it) {
            const int i = w * 72 + it * 3 + g;
            float u[DDIM];
            if (active) {
                const float4* up =
                    reinterpret_cast<const float4*>(ubase + (size_t)i * FDIM + j * DDIM);
                const float4 u0 = up[0], u1 = up[1], u2 = up[2], u3 = up[3];
                u[0]=u0.x; u[1]=u0.y; u[2]=u0.z; u[3]=u0.w;
                u[4]=u1.x; u[5]=u1.y; u[6]=u1.z; u[7]=u1.w;
                u[8]=u2.x; u[9]=u2.y; u[10]=u2.z; u[11]=u2.w;
                u[12]=u3.x; u[13]=u3.y; u[14]=u3.z; u[15]=u3.w;
            } else {
#pragma unroll
                for (int d = 0; d < DDIM; d++) u[d] = 0.f;
            }

            if (pass == 0) {
                // c = 1/NOUT uniform -> plain sum; scale applied later
#pragma unroll
                for (int d = 0; d < DDIM; d++) sacc[d] += u[d];
            } else {
                // logit for (i, j): u . vsum
                float a = 0.f;
#pragma unroll
                for (int d = 0; d < DDIM; d++) a = fmaf(u[d], vr[d], a);
                // gather the 10 logits of this group's i
                float av[NOUT];
#pragma unroll
                for (int jj = 0; jj < NOUT; jj++)
                    av[jj] = __shfl_sync(FULL, a, g * 10 + jj);
                float amax = av[0];
#pragma unroll
                for (int jj = 1; jj < NOUT; jj++) amax = fmaxf(amax, av[jj]);
                const float e = __expf(a - amax);
                float esum = 0.f;
#pragma unroll
                for (int jj = 0; jj < NOUT; jj++)
                    esum += __shfl_sync(FULL, e, g * 10 + jj);
                const float c = __fdividef(e, esum);
#pragma unroll
                for (int d = 0; d < DDIM; d++) sacc[d] = fmaf(c, u[d], sacc[d]);
            }
        }

        // combine the 3 groups (lanes l, l+10, l+20) -> lanes 0..9
#pragma unroll
        for (int d = 0; d < DDIM; d++) {
            const float t1 = __shfl_down_sync(FULL, sacc[d], 10);
            const float t2 = __shfl_down_sync(FULL, sacc[d], 20);
            sacc[d] += t1 + t2;
        }
        if (l < NOUT) {
#pragma unroll
            for (int d = 0; d < DDIM; d++) s_part[w][l * DDIM + d] = sacc[d];
        }
        __syncthreads();

        // reduce across warps + bias
        if (tid < FDIM) {
            float acc = 0.f;
#pragma unroll
            for (int ww = 0; ww < 16; ww++) acc += s_part[ww][tid];
            if (pass == 0) acc *= (1.0f / NOUT);
            s_red[tid] = acc + bias_sm[tid];
        }
        __syncthreads();

        // squash (10 lanes of warp 0)
        if (tid < NOUT) {
            float sv[DDIM];
            float sq = 0.f;
#pragma unroll
            for (int d = 0; d < DDIM; d++) {
                sv[d] = s_red[tid * DDIM + d];
                sq = fmaf(sv[d], sv[d], sq);
            }
            const float scale = sq / (1.0f + sq) * rsqrtf(sq + SQ_EPS);
#pragma unroll
            for (int d = 0; d < DDIM; d++) {
                const float v = scale * sv[d];
                vlast_sm[tid * DDIM + d] = v;
                if (pass == 0)      vsum_sm[tid * DDIM + d] = v;
                else if (pass == 1) vsum_sm[tid * DDIM + d] += v;
            }
        }
        __syncthreads();
    }

    if (tid < FDIM) out[(size_t)b * FDIM + tid] = vlast_sm[tid];
}

// ---------------------------------------------------------------------------
extern "C" void kernel_launch(void* const* d_in, const int* in_sizes, int n_in,
                              void* d_out, int out_size) {
    const float* x = nullptr;
    const float* W = nullptr;
    const float* bias = nullptr;
    for (int idx = 0; idx < n_in; ++idx) {
        if (in_sizes[idx] == BATCH * NIN * DIN)             x    = (const float*)d_in[idx];
        else if (in_sizes[idx] == NIN * NOUT * DDIM * DIN)  W    = (const float*)d_in[idx];
        else if (in_sizes[idx] == NOUT * DDIM)              bias = (const float*)d_in[idx];
    }
    k1_uhat<<<NIN, 320>>>(x, W);
    k2_route<<<BATCH, 512>>>(bias, (float*)d_out);
}

// round 2
// speedup vs baseline: 1.7021x; 1.7021x over previous
#include <cuda_runtime.h>
#include <cuda_fp16.h>

// Problem constants
#define BATCH 128
#define NIN   1152
#define DIN   8
#define NOUT  10
#define DDIM  16
#define FDIM  160          // NOUT*DDIM
#define SQ_EPS 1e-7f

#define K2_THREADS 768
#define K2_WARPS   24
#define I_PER_WARP 48      // NIN / K2_WARPS
#define K2_ITERS   16      // I_PER_WARP / 3

// u_hat scratch: [BATCH][NIN][NOUT*DDIM] fp16 = 47.2 MB (fully L2-resident)
__device__ __half g_uhat[(size_t)BATCH * NIN * FDIM];

// ---------------------------------------------------------------------------
// K1: u_hat[b,i,j,d] = sum_k W[i,j,d,k] * x[b,i,k]  -> fp16 store
// One block per input capsule i. Each thread owns a PAIR of f-slots so it can
// emit one __half2 (4B) store -> fully coalesced.
// ---------------------------------------------------------------------------
__global__ __launch_bounds__(320) void k1_uhat(const float* __restrict__ x,
                                               const float* __restrict__ W) {
    const int i = blockIdx.x;                 // 0..1151
    __shared__ __align__(16) float Ws[FDIM * DIN];   // 5 KB
    __shared__ __align__(16) float xs[BATCH * DIN];  // 4 KB
    const int tid = threadIdx.x;

    for (int t = tid; t < FDIM * DIN; t += 320)
        Ws[t] = W[(size_t)i * (FDIM * DIN) + t];
    for (int t = tid; t < BATCH * DIN; t += 320) {
        const int b = t / DIN, k = t % DIN;
        xs[t] = x[((size_t)b * NIN + i) * DIN + k];
    }
    __syncthreads();

    const int f2 = tid % 80;   // pair index: covers f = 2*f2, 2*f2+1
    const int b0 = tid / 80;   // 0..3

    float wA[DIN], wB[DIN];
#pragma unroll
    for (int k = 0; k < DIN; k++) {
        wA[k] = Ws[(2 * f2) * DIN + k];
        wB[k] = Ws[(2 * f2 + 1) * DIN + k];
    }

    __half2* __restrict__ uh2 = reinterpret_cast<__half2*>(g_uhat);

    for (int b = b0; b < BATCH; b += 4) {
        const float4 xa = *reinterpret_cast<const float4*>(&xs[b * DIN]);
        const float4 xb = *reinterpret_cast<const float4*>(&xs[b * DIN + 4]);
        float a0 = wA[0] * xa.x, a1 = wB[0] * xa.x;
        a0 = fmaf(wA[1], xa.y, a0);  a1 = fmaf(wB[1], xa.y, a1);
        a0 = fmaf(wA[2], xa.z, a0);  a1 = fmaf(wB[2], xa.z, a1);
        a0 = fmaf(wA[3], xa.w, a0);  a1 = fmaf(wB[3], xa.w, a1);
        a0 = fmaf(wA[4], xb.x, a0);  a1 = fmaf(wB[4], xb.x, a1);
        a0 = fmaf(wA[5], xb.y, a0);  a1 = fmaf(wB[5], xb.y, a1);
        a0 = fmaf(wA[6], xb.z, a0);  a1 = fmaf(wB[6], xb.z, a1);
        a0 = fmaf(wA[7], xb.w, a0);  a1 = fmaf(wB[7], xb.w, a1);
        uh2[((size_t)b * NIN + i) * (FDIM / 2) + f2] = __floats2half2_rn(a0, a1);
    }
}

// ---------------------------------------------------------------------------
// K2: fused 3-iteration dynamic routing. One block (768 thr = 24 warps) per b.
// Logits never materialized: b_t(i,j) = u_hat[i,j,:] . (v0+...+v_{t-1}).
// Warp layout: 3 groups x 10 lanes; lane owns capsule j (16 halfs = 32B,
// 2x LDG.128 per lane, software-pipelined).
// ---------------------------------------------------------------------------
__global__ __launch_bounds__(K2_THREADS) void k2_route(const float* __restrict__ bias,
                                                       float* __restrict__ out) {
    const int b   = blockIdx.x;
    const int tid = threadIdx.x;
    const int w   = tid >> 5;        // warp 0..23
    const int l   = tid & 31;        // lane
    const bool active = (l < 30);
    const int g = active ? (l / 10) : 0;   // group 0..2
    const int j = active ? (l % 10) : 0;   // output capsule

    __shared__ float s_part[K2_WARPS][FDIM];  // 15 KB
    __shared__ float s_red[FDIM];
    __shared__ float vsum_sm[FDIM];           // v0 + v1 (+...)
    __shared__ float vlast_sm[FDIM];
    __shared__ float bias_sm[FDIM];

    if (tid < FDIM) bias_sm[tid] = bias[tid];

    const __half* __restrict__ ubase = g_uhat + (size_t)b * NIN * FDIM;
    const unsigned FULL = 0xFFFFFFFFu;

    for (int pass = 0; pass < 3; ++pass) {
        float vr[DDIM];
        if (pass > 0) {
#pragma unroll
            for (int d = 0; d < DDIM; d++) vr[d] = vsum_sm[j * DDIM + d];
        }
        float sacc[DDIM];
#pragma unroll
        for (int d = 0; d < DDIM; d++) sacc[d] = 0.f;

        // prologue: load iter 0 (32B = 2x uint4 per lane)
        uint4 p0 = make_uint4(0, 0, 0, 0), p1 = make_uint4(0, 0, 0, 0);
        {
            const int i = w * I_PER_WARP + g;
            if (active) {
                const uint4* up = reinterpret_cast<const uint4*>(
                    ubase + (size_t)i * FDIM + j * DDIM);
                p0 = up[0];
                p1 = up[1];
            }
        }

        for (int it = 0; it < K2_ITERS; ++it) {
            // prefetch next iteration
            uint4 n0 = make_uint4(0, 0, 0, 0), n1 = make_uint4(0, 0, 0, 0);
            if (it + 1 < K2_ITERS && active) {
                const int ni = w * I_PER_WARP + (it + 1) * 3 + g;
                const uint4* up = reinterpret_cast<const uint4*>(
                    ubase + (size_t)ni * FDIM + j * DDIM);
                n0 = up[0];
                n1 = up[1];
            }

            // convert current tile fp16 -> fp32
            float u[DDIM];
            {
                const __half2* h0 = reinterpret_cast<const __half2*>(&p0);
                const __half2* h1 = reinterpret_cast<const __half2*>(&p1);
#pragma unroll
                for (int m = 0; m < 4; m++) {
                    float2 f0 = __half22float2(h0[m]);
                    float2 f1 = __half22float2(h1[m]);
                    u[2 * m]     = f0.x;  u[2 * m + 1]     = f0.y;
                    u[8 + 2 * m] = f1.x;  u[8 + 2 * m + 1] = f1.y;
                }
            }

            if (pass == 0) {
#pragma unroll
                for (int d = 0; d < DDIM; d++) sacc[d] += u[d];
            } else {
                float a = 0.f;
#pragma unroll
                for (int d = 0; d < DDIM; d++) a = fmaf(u[d], vr[d], a);
                float av[NOUT];
#pragma unroll
                for (int jj = 0; jj < NOUT; jj++)
                    av[jj] = __shfl_sync(FULL, a, g * 10 + jj);
                float amax = av[0];
#pragma unroll
                for (int jj = 1; jj < NOUT; jj++) amax = fmaxf(amax, av[jj]);
                const float e = __expf(a - amax);
                float esum = 0.f;
#pragma unroll
                for (int jj = 0; jj < NOUT; jj++)
                    esum += __shfl_sync(FULL, e, g * 10 + jj);
                const float c = __fdividef(e, esum);
#pragma unroll
                for (int d = 0; d < DDIM; d++) sacc[d] = fmaf(c, u[d], sacc[d]);
            }
            p0 = n0;
            p1 = n1;
        }

        // combine 3 groups (lanes l, l+10, l+20) -> lanes 0..9
#pragma unroll
        for (int d = 0; d < DDIM; d++) {
            const float t1 = __shfl_down_sync(FULL, sacc[d], 10);
            const float t2 = __shfl_down_sync(FULL, sacc[d], 20);
            sacc[d] += t1 + t2;
        }
        if (l < NOUT) {
#pragma unroll
            for (int d = 0; d < DDIM; d++) s_part[w][l * DDIM + d] = sacc[d];
        }
        __syncthreads();

        // reduce across warps + bias
        if (tid < FDIM) {
            float acc = 0.f;
#pragma unroll
            for (int ww = 0; ww < K2_WARPS; ww++) acc += s_part[ww][tid];
            if (pass == 0) acc *= (1.0f / NOUT);
            s_red[tid] = acc + bias_sm[tid];
        }
        __syncthreads();

        // squash (10 lanes)
        if (tid < NOUT) {
            float sv[DDIM];
            float sq = 0.f;
#pragma unroll
            for (int d = 0; d < DDIM; d++) {
                sv[d] = s_red[tid * DDIM + d];
                sq = fmaf(sv[d], sv[d], sq);
            }
            const float scale = sq / (1.0f + sq) * rsqrtf(sq + SQ_EPS);
#pragma unroll
            for (int d = 0; d < DDIM; d++) {
                const float v = scale * sv[d];
                vlast_sm[tid * DDIM + d] = v;
                if (pass == 0)      vsum_sm[tid * DDIM + d] = v;
                else if (pass == 1) vsum_sm[tid * DDIM + d] += v;
            }
        }
        __syncthreads();
    }

    if (tid < FDIM) out[(size_t)b * FDIM + tid] = vlast_sm[tid];
}

// ---------------------------------------------------------------------------
extern "C" void kernel_launch(void* const* d_in, const int* in_sizes, int n_in,
                              void* d_out, int out_size) {
    const float* x = nullptr;
    const float* W = nullptr;
    const float* bias = nullptr;
    for (int idx = 0; idx < n_in; ++idx) {
        if (in_sizes[idx] == BATCH * NIN * DIN)             x    = (const float*)d_in[idx];
        else if (in_sizes[idx] == NIN * NOUT * DDIM * DIN)  W    = (const float*)d_in[idx];
        else if (in_sizes[idx] == NOUT * DDIM)              bias = (const float*)d_in[idx];
    }
    k1_uhat<<<NIN, 320>>>(x, W);
    k2_route<<<BATCH, K2_THREADS>>>(bias, (float*)d_out);
}

// round 3
// speedup vs baseline: 1.7742x; 1.0423x over previous
#include <cuda_runtime.h>
#include <cuda_fp16.h>

// Problem constants
#define BATCH 128
#define NIN   1152
#define DIN   8
#define NOUT  10
#define DDIM  16
#define FDIM  160          // NOUT*DDIM
#define ROWSZ ((size_t)NIN * FDIM)   // 184320, elems per batch row of u_hat
#define SQ_EPS 1e-7f

#define K2_THREADS 768
#define K2_WARPS   24
#define I_PER_WARP 48      // NIN / K2_WARPS
#define K2_ITERS   16      // I_PER_WARP / 3

typedef unsigned long long ull;

// u_hat scratch: [BATCH][NIN][NOUT*DDIM] fp16 = 47.2 MB (L2-resident)
__device__ __half g_uhat[(size_t)BATCH * ROWSZ];

// ---------------- packed f32x2 helpers (ptxas won't auto-fuse) -------------
__device__ __forceinline__ ull pk2(float lo, float hi) {
    ull r; asm("mov.b64 %0, {%1, %2};" : "=l"(r) : "f"(lo), "f"(hi)); return r;
}
__device__ __forceinline__ void upk2(ull v, float& lo, float& hi) {
    asm("mov.b64 {%0, %1}, %2;" : "=f"(lo), "=f"(hi) : "l"(v));
}
__device__ __forceinline__ ull fma2(ull a, ull b, ull c) {
    ull d; asm("fma.rn.f32x2 %0, %1, %2, %3;" : "=l"(d) : "l"(a), "l"(b), "l"(c)); return d;
}
__device__ __forceinline__ ull mul2(ull a, ull b) {
    ull d; asm("mul.rn.f32x2 %0, %1, %2;" : "=l"(d) : "l"(a), "l"(b)); return d;
}
__device__ __forceinline__ ull add2(ull a, ull b) {
    ull d; asm("add.rn.f32x2 %0, %1, %2;" : "=l"(d) : "l"(a), "l"(b)); return d;
}
// half2 (as u32) -> packed f32x2
__device__ __forceinline__ ull h2_to_f2(unsigned h2) {
    ull r;
    asm("{\n\t"
        ".reg .b16 l, h;\n\t"
        ".reg .f32 fl, fh;\n\t"
        "mov.b32 {l, h}, %1;\n\t"
        "cvt.f32.f16 fl, l;\n\t"
        "cvt.f32.f16 fh, h;\n\t"
        "mov.b64 %0, {fl, fh};\n\t"
        "}" : "=l"(r) : "r"(h2));
    return r;
}

// ---------------------------------------------------------------------------
// K1: u_hat[b,i,f] = sum_k W[i,f,k] * x[b,i,k], fp16 store.
// One block per i. b-PAIRED f32x2: acc2=(acc_b0,acc_b1); x transposed in SMEM
// so the (x[b0,k],x[b1,k]) pair is a single ld.shared.b64; w packed (w,w) once.
// ---------------------------------------------------------------------------
__global__ __launch_bounds__(320) void k1_uhat(const float* __restrict__ x,
                                               const float* __restrict__ W) {
    const int i = blockIdx.x;                 // 0..1151
    __shared__ __align__(16) float Ws[FDIM * DIN];   // 5 KB
    __shared__ __align__(16) float xt[DIN][BATCH];   // 4 KB, transposed [k][b]
    const int tid = threadIdx.x;

    for (int t = tid; t < FDIM * DIN; t += 320)
        Ws[t] = W[(size_t)i * (FDIM * DIN) + t];
    for (int t = tid; t < BATCH * DIN; t += 320) {
        const int b = t >> 3, k = t & 7;
        xt[k][b] = x[((size_t)b * NIN + i) * DIN + k];
    }
    __syncthreads();

    const int f  = tid % FDIM;   // one f per thread
    const int p0 = tid / FDIM;   // b-pair phase 0/1

    ull w2[DIN];
#pragma unroll
    for (int k = 0; k < DIN; k++) {
        const float w = Ws[f * DIN + k];
        w2[k] = pk2(w, w);
    }

    __half* __restrict__ ubase = g_uhat + (size_t)i * FDIM + f;

    for (int p = p0; p < BATCH / 2; p += 2) {
        const int b = 2 * p;
        ull acc = mul2(w2[0], *reinterpret_cast<const ull*>(&xt[0][b]));
#pragma unroll
        for (int k = 1; k < DIN; k++)
            acc = fma2(w2[k], *reinterpret_cast<const ull*>(&xt[k][b]), acc);
        float a0, a1; upk2(acc, a0, a1);
        ubase[(size_t)b * ROWSZ]       = __float2half_rn(a0);
        ubase[(size_t)(b + 1) * ROWSZ] = __float2half_rn(a1);
    }
}

// ---------------------------------------------------------------------------
// K2: fused 3-iteration dynamic routing, one block (768 thr) per b.
// Logits never materialized: b_t(i,j) = u_hat[i,j,:] . (v0+...+v_{t-1}).
// Warp layout: 3 groups x 10 lanes; lane owns capsule j. f32x2 math,
// clamped softmax (no max-subtract), fp16 loads software-pipelined.
// ---------------------------------------------------------------------------
__global__ __launch_bounds__(K2_THREADS) void k2_route(const float* __restrict__ bias,
                                                       float* __restrict__ out) {
    const int b   = blockIdx.x;
    const int tid = threadIdx.x;
    const int w   = tid >> 5;
    const int l   = tid & 31;
    const bool active = (l < 30);
    const int g = active ? (l / 10) : 0;
    const int j = active ? (l % 10) : 0;

    __shared__ float s_part[K2_WARPS][FDIM];  // 15 KB
    __shared__ float s_red[FDIM];
    __shared__ float vsum_sm[FDIM];
    __shared__ float vlast_sm[FDIM];
    __shared__ float bias_sm[FDIM];

    if (tid < FDIM) bias_sm[tid] = bias[tid];

    const __half* __restrict__ ubase = g_uhat + (size_t)b * ROWSZ;
    const unsigned FULL = 0xFFFFFFFFu;

    for (int pass = 0; pass < 3; ++pass) {
        ull vr2[8];
        if (pass > 0) {
#pragma unroll
            for (int m = 0; m < 8; m++)
                vr2[m] = pk2(vsum_sm[j * DDIM + 2 * m], vsum_sm[j * DDIM + 2 * m + 1]);
        }
        ull sacc2[8];
#pragma unroll
        for (int m = 0; m < 8; m++) sacc2[m] = 0ull;   // +0.0,+0.0

        // prologue: iter-0 load (32B per lane)
        uint4 p0 = make_uint4(0, 0, 0, 0), p1 = make_uint4(0, 0, 0, 0);
        {
            const int i = w * I_PER_WARP + g;
            if (active) {
                const uint4* up = reinterpret_cast<const uint4*>(
                    ubase + (size_t)i * FDIM + j * DDIM);
                p0 = up[0]; p1 = up[1];
            }
        }

        for (int it = 0; it < K2_ITERS; ++it) {
            uint4 n0 = make_uint4(0, 0, 0, 0), n1 = make_uint4(0, 0, 0, 0);
            if (it + 1 < K2_ITERS && active) {
                const int ni = w * I_PER_WARP + (it + 1) * 3 + g;
                const uint4* up = reinterpret_cast<const uint4*>(
                    ubase + (size_t)ni * FDIM + j * DDIM);
                n0 = up[0]; n1 = up[1];
            }

            // fp16 -> packed f32x2 (pair layout matches d even/odd)
            ull u2[8];
            u2[0] = h2_to_f2(p0.x); u2[1] = h2_to_f2(p0.y);
            u2[2] = h2_to_f2(p0.z); u2[3] = h2_to_f2(p0.w);
            u2[4] = h2_to_f2(p1.x); u2[5] = h2_to_f2(p1.y);
            u2[6] = h2_to_f2(p1.z); u2[7] = h2_to_f2(p1.w);

            if (pass == 0) {
#pragma unroll
                for (int m = 0; m < 8; m++) sacc2[m] = add2(sacc2[m], u2[m]);
            } else {
                // logit a = u . vsum  (packed dot)
                ull a2 = mul2(u2[0], vr2[0]);
#pragma unroll
                for (int m = 1; m < 8; m++) a2 = fma2(u2[m], vr2[m], a2);
                float alo, ahi; upk2(a2, alo, ahi);
                float a = alo + ahi;
                // clamped softmax over group's 10 lanes (shift-invariant; no max)
                a = fmaxf(fminf(a, 60.f), -60.f);
                const float e = __expf(a);
                float esum = 0.f;
#pragma unroll
                for (int jj = 0; jj < NOUT; jj++)
                    esum += __shfl_sync(FULL, e, g * 10 + jj);
                const float c = __fdividef(e, esum);
                const ull c2 = pk2(c, c);
#pragma unroll
                for (int m = 0; m < 8; m++) sacc2[m] = fma2(c2, u2[m], sacc2[m]);
            }
            p0 = n0; p1 = n1;
        }

        // combine 3 groups (lanes l, l+10, l+20) -> lanes 0..9 (64-bit shuffles)
#pragma unroll
        for (int m = 0; m < 8; m++) {
            const ull t1 = __shfl_down_sync(FULL, sacc2[m], 10);
            const ull t2 = __shfl_down_sync(FULL, sacc2[m], 20);
            sacc2[m] = add2(sacc2[m], add2(t1, t2));
        }
        if (l < NOUT) {
#pragma unroll
            for (int m = 0; m < 8; m++)
                *reinterpret_cast<ull*>(&s_part[w][l * DDIM + 2 * m]) = sacc2[m];
        }
        __syncthreads();

        // reduce across warps + bias
        if (tid < FDIM) {
            float acc = 0.f;
#pragma unroll
            for (int ww = 0; ww < K2_WARPS; ww++) acc += s_part[ww][tid];
            if (pass == 0) acc *= (1.0f / NOUT);
            s_red[tid] = acc + bias_sm[tid];
        }
        __syncthreads();

        // squash (10 lanes)
        if (tid < NOUT) {
            float sv[DDIM];
            float sq = 0.f;
#pragma unroll
            for (int d = 0; d < DDIM; d++) {
                sv[d] = s_red[tid * DDIM + d];
                sq = fmaf(sv[d], sv[d], sq);
            }
            const float scale = sq / (1.0f + sq) * rsqrtf(sq + SQ_EPS);
#pragma unroll
            for (int d = 0; d < DDIM; d++) {
                const float v = scale * sv[d];
                vlast_sm[tid * DDIM + d] = v;
                if (pass == 0)      vsum_sm[tid * DDIM + d] = v;
                else if (pass == 1) vsum_sm[tid * DDIM + d] += v;
            }
        }
        __syncthreads();
    }

    if (tid < FDIM) out[(size_t)b * FDIM + tid] = vlast_sm[tid];
}

// ---------------------------------------------------------------------------
extern "C" void kernel_launch(void* const* d_in, const int* in_sizes, int n_in,
                              void* d_out, int out_size) {
    const float* x = nullptr;
    const float* W = nullptr;
    const float* bias = nullptr;
    for (int idx = 0; idx < n_in; ++idx) {
        if (in_sizes[idx] == BATCH * NIN * DIN)             x    = (const float*)d_in[idx];
        else if (in_sizes[idx] == NIN * NOUT * DDIM * DIN)  W    = (const float*)d_in[idx];
        else if (in_sizes[idx] == NOUT * DDIM)              bias = (const float*)d_in[idx];
    }
    k1_uhat<<<NIN, 320>>>(x, W);
    k2_route<<<BATCH, K2_THREADS>>>(bias, (float*)d_out);
}